// round 14
// baseline (speedup 1.0000x reference)
#include <cuda_runtime.h>
#include <cuda_bf16.h>
#include <cstdint>

// ---------------- problem constants ----------------
#define N_NODES   50000
#define N_EDGES   800000
#define N_GRAPHS  64
#define IN_DIM    128
#define HID       256
#define N_LAYERS  4
#define NPAD      50048   // 64*782 = 128*391
#define NB        196

// fp8 fragment-ordered weights (u32 slots, each = 4 x e4m3)
#define EMB_F8    (4*32*32*2)     // ktiles(32-chunks)=4
#define LYR_F8    (16*32*32*2)    // ktiles=16
#define WF8_U32   (EMB_F8 + 4*LYR_F8)

#define XSCL 8.0f     // x stored in fp8 as 8*x
#define WSCL 16.0f    // W stored in fp8 as 16*W
#define INV_XW (1.0f/(XSCL*WSCL))
#define INV_W  (1.0f/WSCL)

#define ASTR 132      // smem A row stride in u32 (conflict-free fragment LDS)

// ---------------- device scratch ----------------
__device__ uint32_t g_xb[(size_t)NPAD * 128];   // bf16 canonical x
__device__ uint32_t g_xf8[(size_t)NPAD * 64];   // e4m3 8*x
__device__ uint32_t g_cf8[(size_t)NPAD * 64];   // e4m3 8*c
__device__ uint32_t g_wf8[WF8_U32];
__device__ int      g_deg[N_NODES];
__device__ int      g_rowoff[N_NODES + 1];
__device__ int      g_cursor[N_NODES];
__device__ int      g_csr[N_EDGES];
__device__ float    g_inv[N_NODES];
__device__ int      g_bsum[NB];
__device__ int      g_boff[NB];
__device__ float    g_hg[N_GRAPHS * HID];
__device__ float    g_gcnt[N_GRAPHS];

// ---------------- helpers ----------------
__device__ __forceinline__ uint32_t pk2(float lo, float hi) {
    uint32_t p;
    asm("cvt.rn.bf16x2.f32 %0, %1, %2;" : "=r"(p) : "f"(hi), "f"(lo));
    return p;
}
__device__ __forceinline__ float blo(uint32_t u) { return __uint_as_float(u << 16); }
__device__ __forceinline__ float bhi(uint32_t u) { return __uint_as_float(u & 0xffff0000u); }

__device__ __forceinline__ unsigned short pk_e2(float f0, float f1) {
    unsigned short d;
    asm("cvt.rn.satfinite.e4m3x2.f32 %0, %1, %2;" : "=h"(d) : "f"(f1), "f"(f0));
    return d;
}
__device__ __forceinline__ uint32_t pk_e4(float f0, float f1, float f2, float f3) {
    unsigned short lo = pk_e2(f0, f1), hi = pk_e2(f2, f3);
    uint32_t r;
    asm("mov.b32 %0, {%1, %2};" : "=r"(r) : "h"(lo), "h"(hi));
    return r;
}
__device__ __forceinline__ void acc_f8(uint32_t v, uint32_t& sA, uint32_t& sB) {
    unsigned short lo, hi;
    asm("mov.b32 {%0, %1}, %2;" : "=h"(lo), "=h"(hi) : "r"(v));
    uint32_t fA, fB;
    asm("cvt.rn.f16x2.e4m3x2 %0, %1;" : "=r"(fA) : "h"(lo));
    asm("cvt.rn.f16x2.e4m3x2 %0, %1;" : "=r"(fB) : "h"(hi));
    asm("add.rn.f16x2 %0, %0, %1;" : "+r"(sA) : "r"(fA));
    asm("add.rn.f16x2 %0, %0, %1;" : "+r"(sB) : "r"(fB));
}
__device__ __forceinline__ void hadd2(uint32_t& a, uint32_t b) {
    asm("add.rn.f16x2 %0, %0, %1;" : "+r"(a) : "r"(b));
}
__device__ __forceinline__ float2 up_h2(uint32_t v) {
    unsigned short lo, hi;
    asm("mov.b32 {%0, %1}, %2;" : "=h"(lo), "=h"(hi) : "r"(v));
    float a, b;
    asm("cvt.f32.f16 %0, %1;" : "=f"(a) : "h"(lo));
    asm("cvt.f32.f16 %0, %1;" : "=f"(b) : "h"(hi));
    return make_float2(a, b);
}

// fp8 MMA with f16 accumulators
__device__ __forceinline__ void mma_f8h(uint32_t* c, const uint32_t* a,
                                        uint32_t b0, uint32_t b1) {
    asm volatile(
        "mma.sync.aligned.m16n8k32.row.col.f16.e4m3.e4m3.f16 "
        "{%0,%1}, {%2,%3,%4,%5}, {%6,%7}, {%0,%1};"
        : "+r"(c[0]), "+r"(c[1])
        : "r"(a[0]), "r"(a[1]), "r"(a[2]), "r"(a[3]), "r"(b0), "r"(b1));
}

// ---------------- init ----------------
__global__ void init_k() {
    int i = blockIdx.x * blockDim.x + threadIdx.x;
    if (i < N_NODES) g_deg[i] = 0;
    if (i < N_GRAPHS * HID) g_hg[i] = 0.0f;
    if (i < N_GRAPHS) g_gcnt[i] = 0.0f;
}

// ---------------- weight prep: x16 scale, e4m3, fragment-ordered ----------
__global__ void prep_k(const float* __restrict__ W_emb,
                       const float* __restrict__ Ws) {
    int i = blockIdx.x * blockDim.x + threadIdx.x;
    if (i >= WF8_U32) return;
    const float* Wsrc;
    int r;
    if (i < EMB_F8) { r = i; Wsrc = W_emb; }
    else {
        int j = i - EMB_F8;
        int l = j / LYR_F8;
        r = j % LYR_F8;
        Wsrc = Ws + (size_t)l * 512 * 256;
    }
    int reg = r & 1;
    int lane = (r >> 1) & 31;
    int tile = r >> 6;
    int nt = tile & 31;
    int kt = tile >> 5;
    int k0 = kt * 32 + (lane & 3) * 4 + reg * 16;
    int n = nt * 8 + (lane >> 2);
    float w0 = Wsrc[(size_t)k0 * 256 + n] * WSCL;
    float w1 = Wsrc[(size_t)(k0 + 1) * 256 + n] * WSCL;
    float w2 = Wsrc[(size_t)(k0 + 2) * 256 + n] * WSCL;
    float w3 = Wsrc[(size_t)(k0 + 3) * 256 + n] * WSCL;
    g_wf8[i] = pk_e4(w0, w1, w2, w3);
}

// ---------------- CSR build ----------------
__global__ void deg_k(const int* __restrict__ dst) {
    int i = blockIdx.x * blockDim.x + threadIdx.x;
    if (i < N_EDGES) atomicAdd(&g_deg[dst[i]], 1);
}

__device__ __forceinline__ int block_scan_incl(int v, int* wt) {
    int t = threadIdx.x;
    int s = v;
    #pragma unroll
    for (int off = 1; off < 32; off <<= 1) {
        int u = __shfl_up_sync(0xffffffffu, s, off);
        if ((t & 31) >= off) s += u;
    }
    if ((t & 31) == 31) wt[t >> 5] = s;
    __syncthreads();
    if (t < 8) {
        int w = wt[t];
        #pragma unroll
        for (int off = 1; off < 8; off <<= 1) {
            int u = __shfl_up_sync(0xffu, w, off);
            if (t >= off) w += u;
        }
        wt[t] = w;
    }
    __syncthreads();
    return s + ((t >= 32) ? wt[(t >> 5) - 1] : 0);
}

__global__ void scanA_k() {
    __shared__ int wt[8];
    int i = blockIdx.x * 256 + threadIdx.x;
    int v = (i < N_NODES) ? g_deg[i] : 0;
    int incl = block_scan_incl(v, wt);
    if (i < N_NODES) g_rowoff[i] = incl - v;
    if (threadIdx.x == 255) g_bsum[blockIdx.x] = incl;
}

__global__ void scanB_k() {
    __shared__ int wt[8];
    int t = threadIdx.x;
    int v = (t < NB) ? g_bsum[t] : 0;
    int incl = block_scan_incl(v, wt);
    if (t < NB) g_boff[t] = incl - v;
    if (t == NB - 1) g_rowoff[N_NODES] = incl;
}

__global__ void scanC_k() {
    int i = blockIdx.x * 256 + threadIdx.x;
    if (i >= N_NODES) return;
    int ro = g_rowoff[i] + g_boff[blockIdx.x];
    g_rowoff[i] = ro;
    g_cursor[i] = ro;
    int d = g_deg[i];
    g_inv[i] = 1.0f / (float)(d > 0 ? d : 1);
}

__global__ void fill_k(const int* __restrict__ src, const int* __restrict__ dst) {
    int i = blockIdx.x * blockDim.x + threadIdx.x;
    if (i < N_EDGES) {
        int d = dst[i];
        int p = atomicAdd(&g_cursor[d], 1);
        g_csr[p] = src[i];
    }
}

// ---------------- mean aggregation: half-warp rows (R7/R11 proven) ---------
__global__ void __launch_bounds__(256) agg_k() {
    int gw = (blockIdx.x * blockDim.x + threadIdx.x) >> 5;
    int lane = threadIdx.x & 31;
    if (gw >= N_NODES) return;
    int half = lane >> 4;
    int hl = lane & 15;
    int beg = g_rowoff[gw];
    int end = g_rowoff[gw + 1];
    uint32_t s[8] = {0, 0, 0, 0, 0, 0, 0, 0};
    const uint4* xf = (const uint4*)g_xf8;
    #pragma unroll 2
    for (int j = beg + half; j < end; j += 2) {
        int sn = g_csr[j];
        uint4 v = xf[(size_t)sn * 16 + hl];
        acc_f8(v.x, s[0], s[1]);
        acc_f8(v.y, s[2], s[3]);
        acc_f8(v.z, s[4], s[5]);
        acc_f8(v.w, s[6], s[7]);
    }
    #pragma unroll
    for (int q = 0; q < 8; q++) {
        uint32_t o = __shfl_xor_sync(0xffffffffu, s[q], 16);
        hadd2(s[q], o);
    }
    if (half == 0) {
        float inv = g_inv[gw];
        float2 a0 = up_h2(s[0]), a1 = up_h2(s[1]);
        float2 a2 = up_h2(s[2]), a3 = up_h2(s[3]);
        float2 a4 = up_h2(s[4]), a5 = up_h2(s[5]);
        float2 a6 = up_h2(s[6]), a7 = up_h2(s[7]);
        uint4 o;
        o.x = pk_e4(a0.x * inv, a0.y * inv, a1.x * inv, a1.y * inv);
        o.y = pk_e4(a2.x * inv, a2.y * inv, a3.x * inv, a3.y * inv);
        o.z = pk_e4(a4.x * inv, a4.y * inv, a5.x * inv, a5.y * inv);
        o.w = pk_e4(a6.x * inv, a6.y * inv, a7.x * inv, a7.y * inv);
        ((uint4*)g_cf8)[(size_t)gw * 16 + hl] = o;
    }
}

// ---------------- fp8 mma.sync fused GEMM, templated M-tile ----------------
// MROWS rows x 256 cols per CTA; 8 warps (2M x 4N); K-chunk = 32; f16 acc.
// A staged in dynamic smem; MODE1 uses MROWS=128 (halves B re-reads).
template <int MODE, int MROWS>
__global__ void __launch_bounds__(256, 2) tgemm_k(const float* __restrict__ Aext,
                                                  const float* __restrict__ bias,
                                                  int fragoff) {
    const int NCH = MODE ? 16 : 4;
    const int MT = MROWS / 32;          // 16-row tiles per m-warp

    extern __shared__ uint32_t As[];    // [MROWS][ASTR]
    __shared__ float ssq[128];
    __shared__ float rinv[128];
    __shared__ float biasS[256];

    int tid = threadIdx.x;
    int lane = tid & 31;
    int wid = tid >> 5;
    int wm = wid >> 2;
    int wn = wid & 3;
    int g = lane >> 2;
    int t = lane & 3;
    int row0 = blockIdx.x * MROWS;

    if (tid < MROWS) ssq[tid] = 0.0f;
    if (tid < 128) {
        float2 bv = ((const float2*)bias)[tid];
        biasS[2 * tid] = bv.x;
        biasS[2 * tid + 1] = bv.y;
    }

    // ---- stage A into smem (coalesced) ----
    if (MODE == 0) {
        #pragma unroll
        for (int it = 0; it < MROWS / 8; it++) {
            int idx = it * 256 + tid;
            int r = idx >> 5;
            int cu = idx & 31;
            int gr = row0 + r;
            float4 f = (gr < N_NODES)
                ? ((const float4*)(Aext + (size_t)gr * 128))[cu]
                : make_float4(0.f, 0.f, 0.f, 0.f);
            As[r * ASTR + cu] = pk_e4(f.x, f.y, f.z, f.w);
        }
    } else {
        #pragma unroll
        for (int it = 0; it < MROWS / 16; it++) {
            int idx = it * 256 + tid;
            int r = idx >> 4;
            int q = idx & 15;
            uint4 vx = ((const uint4*)g_xf8)[(size_t)(row0 + r) * 16 + q];
            *(uint4*)&As[r * ASTR + q * 4] = vx;
            uint4 vc = ((const uint4*)g_cf8)[(size_t)(row0 + r) * 16 + q];
            *(uint4*)&As[r * ASTR + 64 + q * 4] = vc;
        }
    }
    __syncthreads();

    uint32_t acc[MT][8][2];
    #pragma unroll
    for (int m = 0; m < MT; m++)
        #pragma unroll
        for (int j = 0; j < 8; j++) {
            acc[m][j][0] = 0u;
            acc[m][j][1] = 0u;
        }

    const uint2* WF = (const uint2*)(g_wf8 + fragoff);
    int bbase = (wn * 8) * 32 + lane;

    #pragma unroll
    for (int ch = 0; ch < NCH; ch++) {
        int base = ch * 8;

        uint2 bh[8];
        const uint2* ph = WF + (size_t)(ch * 32) * 32 + bbase;
        #pragma unroll
        for (int j = 0; j < 8; j++) bh[j] = ph[j * 32];

        #pragma unroll
        for (int mt = 0; mt < MT; mt++) {
            int rl = wm * (MROWS / 2) + mt * 16 + g;
            const uint32_t* p = &As[rl * ASTR + base + t];
            uint32_t ah[4];
            ah[0] = p[0];
            ah[1] = p[8 * ASTR];
            ah[2] = p[4];
            ah[3] = p[8 * ASTR + 4];
            #pragma unroll
            for (int j = 0; j < 8; j++)
                mma_f8h(acc[mt][j], ah, bh[j].x, bh[j].y);
        }
    }

    __syncthreads();

    const float cs = MODE ? INV_XW : INV_W;

    if (MODE == 1) {
        #pragma unroll
        for (int mt = 0; mt < MT; mt++) {
            float p0 = 0.f, p1 = 0.f;
            #pragma unroll
            for (int j = 0; j < 8; j++) {
                int n0 = wn * 64 + j * 8 + 2 * t;
                float b0 = biasS[n0], b1 = biasS[n0 + 1];
                float2 lo = up_h2(acc[mt][j][0]);
                float2 hi = up_h2(acc[mt][j][1]);
                float v0 = lo.x * cs + b0;
                float v1 = lo.y * cs + b1;
                float v2 = hi.x * cs + b0;
                float v3 = hi.y * cs + b1;
                p0 += v0 * v0 + v1 * v1;
                p1 += v2 * v2 + v3 * v3;
            }
            p0 += __shfl_xor_sync(0xffffffffu, p0, 1);
            p0 += __shfl_xor_sync(0xffffffffu, p0, 2);
            p1 += __shfl_xor_sync(0xffffffffu, p1, 1);
            p1 += __shfl_xor_sync(0xffffffffu, p1, 2);
            if (t == 0) {
                atomicAdd(&ssq[wm * (MROWS / 2) + mt * 16 + g], p0);
                atomicAdd(&ssq[wm * (MROWS / 2) + mt * 16 + 8 + g], p1);
            }
        }
        __syncthreads();
        if (tid < MROWS) rinv[tid] = 1.0f / fmaxf(sqrtf(ssq[tid]), 1e-12f);
        __syncthreads();
    }

    unsigned short* xf16 = (unsigned short*)g_xf8;

    #pragma unroll
    for (int mt = 0; mt < MT; mt++) {
        int rl = wm * (MROWS / 2) + mt * 16 + g;
        int r = row0 + rl;
        float i0 = (MODE == 1) ? rinv[rl] : 0.f;
        float i1 = (MODE == 1) ? rinv[rl + 8] : 0.f;
        #pragma unroll
        for (int j = 0; j < 8; j++) {
            int n0 = wn * 64 + j * 8 + 2 * t;
            float b0 = biasS[n0], b1 = biasS[n0 + 1];
            float2 lo = up_h2(acc[mt][j][0]);
            float2 hi = up_h2(acc[mt][j][1]);
            float v0 = lo.x * cs + b0;
            float v1 = lo.y * cs + b1;
            float v2 = hi.x * cs + b0;
            float v3 = hi.y * cs + b1;
            size_t u0 = (size_t)r * 128 + n0 / 2;
            size_t u1 = (size_t)(r + 8) * 128 + n0 / 2;
            if (MODE == 0) {
                g_xb[u0] = pk2(v0, v1);
                g_xb[u1] = pk2(v2, v3);
                xf16[u0] = pk_e2(v0 * XSCL, v1 * XSCL);
                xf16[u1] = pk_e2(v2 * XSCL, v3 * XSCL);
            } else {
                uint32_t xw0 = g_xb[u0];
                float o0 = blo(xw0) + fmaxf(v0, 0.f) * i0;
                float o1 = bhi(xw0) + fmaxf(v1, 0.f) * i0;
                g_xb[u0] = pk2(o0, o1);
                xf16[u0] = pk_e2(o0 * XSCL, o1 * XSCL);
                uint32_t xw1 = g_xb[u1];
                float o2 = blo(xw1) + fmaxf(v2, 0.f) * i1;
                float o3 = bhi(xw1) + fmaxf(v3, 0.f) * i1;
                g_xb[u1] = pk2(o2, o3);
                xf16[u1] = pk_e2(o2 * XSCL, o3 * XSCL);
            }
        }
    }
}

// ---------------- graph mean pool (sorted graph_id, run-length fused) ------
__global__ void accum_k(const int* __restrict__ gid) {
    int b = blockIdx.x;
    int c = threadIdx.x;
    int n0 = b * 256;
    int n1 = min(n0 + 256, N_NODES);
    float sum = 0.0f, cnt = 0.0f;
    int cur = gid[n0];
    for (int n = n0; n < n1; n++) {
        int gg = gid[n];
        if (gg != cur) {
            atomicAdd(&g_hg[cur * HID + c], sum);
            if (c == 0) atomicAdd(&g_gcnt[cur], cnt);
            sum = 0.0f; cnt = 0.0f; cur = gg;
        }
        uint32_t w = g_xb[(size_t)n * 128 + (c >> 1)];
        sum += (c & 1) ? bhi(w) : blo(w);
        cnt += 1.0f;
    }
    atomicAdd(&g_hg[cur * HID + c], sum);
    if (c == 0) atomicAdd(&g_gcnt[cur], cnt);
}

__global__ void final_k(const float* __restrict__ p_pos,
                        const float* __restrict__ p_neg,
                        const float* __restrict__ W_fc,
                        float* __restrict__ out) {
    __shared__ float ss[N_GRAPHS][10];
    int t = threadIdx.x;
    if (t < N_GRAPHS * 10) {
        int g = t / 10;
        int p = t % 10;
        const float* P = (p < 5) ? (p_pos + p * HID) : (p_neg + (p - 5) * HID);
        float invc = 1.0f / fmaxf(g_gcnt[g], 1.0f);
        float d = 0.0f;
        for (int c = 0; c < HID; c++) {
            float diff = g_hg[g * HID + c] * invc - P[c];
            d += diff * diff;
        }
        ss[g][p] = logf((d + 1.0f) / (d + 1e-12f));
    }
    __syncthreads();
    if (t < N_GRAPHS) {
        float y = 0.0f;
        #pragma unroll
        for (int j = 0; j < 10; j++) y += ss[t][j] * W_fc[j];
        out[t] = 1.0f / (1.0f + expf(-y));
    }
}

// ---------------- launch ----------------
extern "C" void kernel_launch(void* const* d_in, const int* in_sizes, int n_in,
                              void* d_out, int out_size) {
    const float* h      = (const float*)d_in[0];
    const int*   src    = (const int*)d_in[1];
    const int*   dst    = (const int*)d_in[2];
    const int*   gid    = (const int*)d_in[3];
    const float* W_emb  = (const float*)d_in[4];
    const float* b_emb  = (const float*)d_in[5];
    const float* Ws     = (const float*)d_in[6];
    const float* bs     = (const float*)d_in[7];
    const float* p_pos  = (const float*)d_in[8];
    const float* p_neg  = (const float*)d_in[9];
    const float* W_fc   = (const float*)d_in[10];
    float* out = (float*)d_out;

    static cudaStream_t s1 = nullptr;
    static cudaEvent_t eFork = nullptr, eJoin = nullptr;
    static bool attrSet = false;
    if (s1 == nullptr) {
        cudaStreamCreateWithFlags(&s1, cudaStreamNonBlocking);
        cudaEventCreateWithFlags(&eFork, cudaEventDisableTiming);
        cudaEventCreateWithFlags(&eJoin, cudaEventDisableTiming);
    }
    if (!attrSet) {
        cudaFuncSetAttribute(tgemm_k<1, 128>,
                             cudaFuncAttributeMaxDynamicSharedMemorySize,
                             128 * ASTR * 4);
        attrSet = true;
    }

    bool fork = (s1 != nullptr && eFork != nullptr && eJoin != nullptr);
    cudaStream_t sb = fork ? s1 : (cudaStream_t)0;

    if (fork) {
        cudaEventRecord(eFork, 0);
        cudaStreamWaitEvent(sb, eFork, 0);
    }

    // branch B (side stream): CSR build + accumulator init
    init_k<<<(N_NODES + 255) / 256, 256, 0, sb>>>();
    deg_k<<<(N_EDGES + 255) / 256, 256, 0, sb>>>(dst);
    scanA_k<<<NB, 256, 0, sb>>>();
    scanB_k<<<1, 256, 0, sb>>>();
    scanC_k<<<NB, 256, 0, sb>>>();
    fill_k<<<(N_EDGES + 255) / 256, 256, 0, sb>>>(src, dst);

    // branch A (main stream): weight prep + embedding GEMM (M=64 tile)
    prep_k<<<(WF8_U32 + 255) / 256, 256>>>(W_emb, Ws);
    tgemm_k<0, 64><<<NPAD / 64, 256, 64 * ASTR * 4>>>(h, b_emb, 0);

    if (fork) {
        cudaEventRecord(eJoin, sb);
        cudaStreamWaitEvent(0, eJoin, 0);
    }

    for (int l = 0; l < N_LAYERS; l++) {
        agg_k<<<(N_NODES * 32 + 255) / 256, 256>>>();
        tgemm_k<1, 128><<<NPAD / 128, 256, 128 * ASTR * 4>>>(
            nullptr, bs + (size_t)l * HID, EMB_F8 + l * LYR_F8);
    }

    accum_k<<<NB, 256>>>(gid);
    final_k<<<1, 640>>>(p_pos, p_neg, W_fc, out);
}

// round 15
// speedup vs baseline: 1.0781x; 1.0781x over previous
#include <cuda_runtime.h>
#include <cuda_bf16.h>
#include <cstdint>

// ---------------- problem constants ----------------
#define N_NODES   50000
#define N_EDGES   800000
#define N_GRAPHS  64
#define IN_DIM    128
#define HID       256
#define N_LAYERS  4
#define NPAD      50048   // 64*782
#define MT64      782
#define NB        196

// fp8 fragment-ordered weights (u32 slots, each = 4 x e4m3)
#define EMB_F8    (4*32*32*2)     // ktiles(32-chunks)=4
#define LYR_F8    (16*32*32*2)    // ktiles=16
#define WF8_U32   (EMB_F8 + 4*LYR_F8)

#define XSCL 8.0f     // x stored in fp8 as 8*x
#define WSCL 16.0f    // W stored in fp8 as 16*W
#define INV_XW (1.0f/(XSCL*WSCL))
#define INV_W  (1.0f/WSCL)

#define ASTR 132      // smem A row stride in u32 (conflict-free fragment LDS)

// ---------------- device scratch ----------------
__device__ uint32_t g_xb[(size_t)NPAD * 128];   // bf16 canonical x
__device__ uint32_t g_xf8[(size_t)NPAD * 64];   // e4m3 8*x
__device__ uint32_t g_cf8[(size_t)NPAD * 64];   // e4m3 8*c
__device__ uint32_t g_wf8[WF8_U32];
__device__ int      g_deg[N_NODES];
__device__ int      g_rowoff[N_NODES + 1];
__device__ int      g_cursor[N_NODES];
__device__ int      g_csr[N_EDGES];
__device__ float    g_inv[N_NODES];
__device__ int      g_bsum[NB];
__device__ int      g_boff[NB];
__device__ float    g_hg[N_GRAPHS * HID];
__device__ float    g_gcnt[N_GRAPHS];

// ---------------- helpers ----------------
__device__ __forceinline__ uint32_t pk2(float lo, float hi) {
    uint32_t p;
    asm("cvt.rn.bf16x2.f32 %0, %1, %2;" : "=r"(p) : "f"(hi), "f"(lo));
    return p;
}
__device__ __forceinline__ float blo(uint32_t u) { return __uint_as_float(u << 16); }
__device__ __forceinline__ float bhi(uint32_t u) { return __uint_as_float(u & 0xffff0000u); }

__device__ __forceinline__ unsigned short pk_e2(float f0, float f1) {
    unsigned short d;
    asm("cvt.rn.satfinite.e4m3x2.f32 %0, %1, %2;" : "=h"(d) : "f"(f1), "f"(f0));
    return d;
}
__device__ __forceinline__ uint32_t pk_e4(float f0, float f1, float f2, float f3) {
    unsigned short lo = pk_e2(f0, f1), hi = pk_e2(f2, f3);
    uint32_t r;
    asm("mov.b32 %0, {%1, %2};" : "=r"(r) : "h"(lo), "h"(hi));
    return r;
}
__device__ __forceinline__ void acc_f8(uint32_t v, uint32_t& sA, uint32_t& sB) {
    unsigned short lo, hi;
    asm("mov.b32 {%0, %1}, %2;" : "=h"(lo), "=h"(hi) : "r"(v));
    uint32_t fA, fB;
    asm("cvt.rn.f16x2.e4m3x2 %0, %1;" : "=r"(fA) : "h"(lo));
    asm("cvt.rn.f16x2.e4m3x2 %0, %1;" : "=r"(fB) : "h"(hi));
    asm("add.rn.f16x2 %0, %0, %1;" : "+r"(sA) : "r"(fA));
    asm("add.rn.f16x2 %0, %0, %1;" : "+r"(sB) : "r"(fB));
}
__device__ __forceinline__ void hadd2(uint32_t& a, uint32_t b) {
    asm("add.rn.f16x2 %0, %0, %1;" : "+r"(a) : "r"(b));
}
__device__ __forceinline__ float2 up_h2(uint32_t v) {
    unsigned short lo, hi;
    asm("mov.b32 {%0, %1}, %2;" : "=h"(lo), "=h"(hi) : "r"(v));
    float a, b;
    asm("cvt.f32.f16 %0, %1;" : "=f"(a) : "h"(lo));
    asm("cvt.f32.f16 %0, %1;" : "=f"(b) : "h"(hi));
    return make_float2(a, b);
}

// fp8 MMA with f16 accumulators: d/c = {f16x2, f16x2} (2 regs)
__device__ __forceinline__ void mma_f8h(uint32_t* c, const uint32_t* a,
                                        uint32_t b0, uint32_t b1) {
    asm volatile(
        "mma.sync.aligned.m16n8k32.row.col.f16.e4m3.e4m3.f16 "
        "{%0,%1}, {%2,%3,%4,%5}, {%6,%7}, {%0,%1};"
        : "+r"(c[0]), "+r"(c[1])
        : "r"(a[0]), "r"(a[1]), "r"(a[2]), "r"(a[3]), "r"(b0), "r"(b1));
}

// ---------------- init ----------------
__global__ void init_k() {
    int i = blockIdx.x * blockDim.x + threadIdx.x;
    if (i < N_NODES) g_deg[i] = 0;
    if (i < N_GRAPHS * HID) g_hg[i] = 0.0f;
    if (i < N_GRAPHS) g_gcnt[i] = 0.0f;
}

// ---------------- weight prep: x16 scale, e4m3, fragment-ordered ----------
__global__ void prep_k(const float* __restrict__ W_emb,
                       const float* __restrict__ Ws) {
    int i = blockIdx.x * blockDim.x + threadIdx.x;
    if (i >= WF8_U32) return;
    const float* Wsrc;
    int r;
    if (i < EMB_F8) { r = i; Wsrc = W_emb; }
    else {
        int j = i - EMB_F8;
        int l = j / LYR_F8;
        r = j % LYR_F8;
        Wsrc = Ws + (size_t)l * 512 * 256;
    }
    int reg = r & 1;
    int lane = (r >> 1) & 31;
    int tile = r >> 6;
    int nt = tile & 31;
    int kt = tile >> 5;
    int k0 = kt * 32 + (lane & 3) * 4 + reg * 16;
    int n = nt * 8 + (lane >> 2);
    float w0 = Wsrc[(size_t)k0 * 256 + n] * WSCL;
    float w1 = Wsrc[(size_t)(k0 + 1) * 256 + n] * WSCL;
    float w2 = Wsrc[(size_t)(k0 + 2) * 256 + n] * WSCL;
    float w3 = Wsrc[(size_t)(k0 + 3) * 256 + n] * WSCL;
    g_wf8[i] = pk_e4(w0, w1, w2, w3);
}

// ---------------- CSR build ----------------
__global__ void deg_k(const int* __restrict__ dst) {
    int i = blockIdx.x * blockDim.x + threadIdx.x;
    if (i < N_EDGES) atomicAdd(&g_deg[dst[i]], 1);
}

__device__ __forceinline__ int block_scan_incl(int v, int* wt) {
    int t = threadIdx.x;
    int s = v;
    #pragma unroll
    for (int off = 1; off < 32; off <<= 1) {
        int u = __shfl_up_sync(0xffffffffu, s, off);
        if ((t & 31) >= off) s += u;
    }
    if ((t & 31) == 31) wt[t >> 5] = s;
    __syncthreads();
    if (t < 8) {
        int w = wt[t];
        #pragma unroll
        for (int off = 1; off < 8; off <<= 1) {
            int u = __shfl_up_sync(0xffu, w, off);
            if (t >= off) w += u;
        }
        wt[t] = w;
    }
    __syncthreads();
    return s + ((t >= 32) ? wt[(t >> 5) - 1] : 0);
}

__global__ void scanA_k() {
    __shared__ int wt[8];
    int i = blockIdx.x * 256 + threadIdx.x;
    int v = (i < N_NODES) ? g_deg[i] : 0;
    int incl = block_scan_incl(v, wt);
    if (i < N_NODES) g_rowoff[i] = incl - v;
    if (threadIdx.x == 255) g_bsum[blockIdx.x] = incl;
}

__global__ void scanB_k() {
    __shared__ int wt[8];
    int t = threadIdx.x;
    int v = (t < NB) ? g_bsum[t] : 0;
    int incl = block_scan_incl(v, wt);
    if (t < NB) g_boff[t] = incl - v;
    if (t == NB - 1) g_rowoff[N_NODES] = incl;
}

__global__ void scanC_k() {
    int i = blockIdx.x * 256 + threadIdx.x;
    if (i >= N_NODES) return;
    int ro = g_rowoff[i] + g_boff[blockIdx.x];
    g_rowoff[i] = ro;
    g_cursor[i] = ro;
    int d = g_deg[i];
    g_inv[i] = 1.0f / (float)(d > 0 ? d : 1);
}

__global__ void fill_k(const int* __restrict__ src, const int* __restrict__ dst) {
    int i = blockIdx.x * blockDim.x + threadIdx.x;
    if (i < N_EDGES) {
        int d = dst[i];
        int p = atomicAdd(&g_cursor[d], 1);
        g_csr[p] = src[i];
    }
}

// ---------------- mean aggregation: half-warp rows (R7/R11/R13 proven) -----
__global__ void __launch_bounds__(256) agg_k() {
    int gw = (blockIdx.x * blockDim.x + threadIdx.x) >> 5;
    int lane = threadIdx.x & 31;
    if (gw >= N_NODES) return;
    int half = lane >> 4;
    int hl = lane & 15;
    int beg = g_rowoff[gw];
    int end = g_rowoff[gw + 1];
    uint32_t s[8] = {0, 0, 0, 0, 0, 0, 0, 0};
    const uint4* xf = (const uint4*)g_xf8;
    #pragma unroll 2
    for (int j = beg + half; j < end; j += 2) {
        int sn = g_csr[j];
        uint4 v = xf[(size_t)sn * 16 + hl];
        acc_f8(v.x, s[0], s[1]);
        acc_f8(v.y, s[2], s[3]);
        acc_f8(v.z, s[4], s[5]);
        acc_f8(v.w, s[6], s[7]);
    }
    #pragma unroll
    for (int q = 0; q < 8; q++) {
        uint32_t o = __shfl_xor_sync(0xffffffffu, s[q], 16);
        hadd2(s[q], o);
    }
    if (half == 0) {
        float inv = g_inv[gw];
        float2 a0 = up_h2(s[0]), a1 = up_h2(s[1]);
        float2 a2 = up_h2(s[2]), a3 = up_h2(s[3]);
        float2 a4 = up_h2(s[4]), a5 = up_h2(s[5]);
        float2 a6 = up_h2(s[6]), a7 = up_h2(s[7]);
        uint4 o;
        o.x = pk_e4(a0.x * inv, a0.y * inv, a1.x * inv, a1.y * inv);
        o.y = pk_e4(a2.x * inv, a2.y * inv, a3.x * inv, a3.y * inv);
        o.z = pk_e4(a4.x * inv, a4.y * inv, a5.x * inv, a5.y * inv);
        o.w = pk_e4(a6.x * inv, a6.y * inv, a7.x * inv, a7.y * inv);
        ((uint4*)g_cf8)[(size_t)gw * 16 + hl] = o;
    }
}

// ---------------- fp8 mma.sync fused GEMM, smem A + f16 acc (R13 proven) ---
// CTA: 256 thr = 8 warps (2M x 4N); tile 64 rows x 256 cols; K-chunk = 32.
// wf8: skip fp8 shadow stores (dead after the last layer).
template <int MODE>
__global__ void __launch_bounds__(256, 3) tgemm_k(const float* __restrict__ Aext,
                                                  const float* __restrict__ bias,
                                                  int fragoff, int wf8) {
    const int NCH = MODE ? 16 : 4;

    __shared__ uint32_t As[64 * ASTR];
    __shared__ float ssq[64];
    __shared__ float rinv[64];
    __shared__ float biasS[256];

    int tid = threadIdx.x;
    int lane = tid & 31;
    int wid = tid >> 5;
    int wm = wid >> 2;
    int wn = wid & 3;
    int g = lane >> 2;
    int t = lane & 3;
    int row0 = blockIdx.x * 64;

    if (tid < 64) ssq[tid] = 0.0f;
    if (tid < 128) {
        float2 bv = ((const float2*)bias)[tid];
        biasS[2 * tid] = bv.x;
        biasS[2 * tid + 1] = bv.y;
    }

    // ---- stage A into smem (coalesced) ----
    if (MODE == 0) {
        #pragma unroll
        for (int it = 0; it < 8; it++) {
            int idx = it * 256 + tid;
            int r = idx >> 5;
            int cu = idx & 31;
            int gr = row0 + r;
            float4 f = (gr < N_NODES)
                ? ((const float4*)(Aext + (size_t)gr * 128))[cu]
                : make_float4(0.f, 0.f, 0.f, 0.f);
            As[r * ASTR + cu] = pk_e4(f.x, f.y, f.z, f.w);
        }
    } else {
        #pragma unroll
        for (int it = 0; it < 4; it++) {
            int idx = it * 256 + tid;
            int r = idx >> 4;
            int q = idx & 15;
            uint4 vx = ((const uint4*)g_xf8)[(size_t)(row0 + r) * 16 + q];
            *(uint4*)&As[r * ASTR + q * 4] = vx;
            uint4 vc = ((const uint4*)g_cf8)[(size_t)(row0 + r) * 16 + q];
            *(uint4*)&As[r * ASTR + 64 + q * 4] = vc;
        }
    }
    __syncthreads();

    uint32_t acc[2][8][2];   // f16x2 pairs
    #pragma unroll
    for (int m = 0; m < 2; m++)
        #pragma unroll
        for (int j = 0; j < 8; j++) {
            acc[m][j][0] = 0u;
            acc[m][j][1] = 0u;
        }

    const uint2* WF = (const uint2*)(g_wf8 + fragoff);
    int bbase = (wn * 8) * 32 + lane;

    #pragma unroll
    for (int ch = 0; ch < NCH; ch++) {
        int base = ch * 8;
        uint32_t ah[2][4];
        #pragma unroll
        for (int mt = 0; mt < 2; mt++) {
            int rl = wm * 32 + mt * 16 + g;
            const uint32_t* p = &As[rl * ASTR + base + t];
            ah[mt][0] = p[0];
            ah[mt][1] = p[8 * ASTR];
            ah[mt][2] = p[4];
            ah[mt][3] = p[8 * ASTR + 4];
        }

        uint2 bh[8];
        const uint2* ph = WF + (size_t)(ch * 32) * 32 + bbase;
        #pragma unroll
        for (int j = 0; j < 8; j++) bh[j] = ph[j * 32];

        #pragma unroll
        for (int mt = 0; mt < 2; mt++)
            #pragma unroll
            for (int j = 0; j < 8; j++)
                mma_f8h(acc[mt][j], ah[mt], bh[j].x, bh[j].y);
    }

    __syncthreads();

    const float cs = MODE ? INV_XW : INV_W;

    if (MODE == 1) {
        #pragma unroll
        for (int mt = 0; mt < 2; mt++) {
            float p0 = 0.f, p1 = 0.f;
            #pragma unroll
            for (int j = 0; j < 8; j++) {
                int n0 = wn * 64 + j * 8 + 2 * t;
                float b0 = biasS[n0], b1 = biasS[n0 + 1];
                float2 lo = up_h2(acc[mt][j][0]);
                float2 hi = up_h2(acc[mt][j][1]);
                float v0 = lo.x * cs + b0;
                float v1 = lo.y * cs + b1;
                float v2 = hi.x * cs + b0;
                float v3 = hi.y * cs + b1;
                p0 += v0 * v0 + v1 * v1;
                p1 += v2 * v2 + v3 * v3;
            }
            p0 += __shfl_xor_sync(0xffffffffu, p0, 1);
            p0 += __shfl_xor_sync(0xffffffffu, p0, 2);
            p1 += __shfl_xor_sync(0xffffffffu, p1, 1);
            p1 += __shfl_xor_sync(0xffffffffu, p1, 2);
            if (t == 0) {
                atomicAdd(&ssq[wm * 32 + mt * 16 + g], p0);
                atomicAdd(&ssq[wm * 32 + mt * 16 + 8 + g], p1);
            }
        }
        __syncthreads();
        if (tid < 64) rinv[tid] = 1.0f / fmaxf(sqrtf(ssq[tid]), 1e-12f);
        __syncthreads();
    }

    unsigned short* xf16 = (unsigned short*)g_xf8;

    #pragma unroll
    for (int mt = 0; mt < 2; mt++) {
        int rl = wm * 32 + mt * 16 + g;
        int r = row0 + rl;
        float i0 = (MODE == 1) ? rinv[rl] : 0.f;
        float i1 = (MODE == 1) ? rinv[rl + 8] : 0.f;
        #pragma unroll
        for (int j = 0; j < 8; j++) {
            int n0 = wn * 64 + j * 8 + 2 * t;
            float b0 = biasS[n0], b1 = biasS[n0 + 1];
            float2 lo = up_h2(acc[mt][j][0]);
            float2 hi = up_h2(acc[mt][j][1]);
            float v0 = lo.x * cs + b0;
            float v1 = lo.y * cs + b1;
            float v2 = hi.x * cs + b0;
            float v3 = hi.y * cs + b1;
            size_t u0 = (size_t)r * 128 + n0 / 2;
            size_t u1 = (size_t)(r + 8) * 128 + n0 / 2;
            if (MODE == 0) {
                g_xb[u0] = pk2(v0, v1);
                g_xb[u1] = pk2(v2, v3);
                xf16[u0] = pk_e2(v0 * XSCL, v1 * XSCL);
                xf16[u1] = pk_e2(v2 * XSCL, v3 * XSCL);
            } else {
                uint32_t xw0 = g_xb[u0];
                float o0 = blo(xw0) + fmaxf(v0, 0.f) * i0;
                float o1 = bhi(xw0) + fmaxf(v1, 0.f) * i0;
                g_xb[u0] = pk2(o0, o1);
                uint32_t xw1 = g_xb[u1];
                float o2 = blo(xw1) + fmaxf(v2, 0.f) * i1;
                float o3 = bhi(xw1) + fmaxf(v3, 0.f) * i1;
                g_xb[u1] = pk2(o2, o3);
                if (wf8) {
                    xf16[u0] = pk_e2(o0 * XSCL, o1 * XSCL);
                    xf16[u1] = pk_e2(o2 * XSCL, o3 * XSCL);
                }
            }
        }
    }
}

// ---------------- graph mean pool (sorted graph_id, run-length fused) ------
__global__ void accum_k(const int* __restrict__ gid) {
    int b = blockIdx.x;
    int c = threadIdx.x;
    int n0 = b * 256;
    int n1 = min(n0 + 256, N_NODES);
    float sum = 0.0f, cnt = 0.0f;
    int cur = gid[n0];
    for (int n = n0; n < n1; n++) {
        int gg = gid[n];
        if (gg != cur) {
            atomicAdd(&g_hg[cur * HID + c], sum);
            if (c == 0) atomicAdd(&g_gcnt[cur], cnt);
            sum = 0.0f; cnt = 0.0f; cur = gg;
        }
        uint32_t w = g_xb[(size_t)n * 128 + (c >> 1)];
        sum += (c & 1) ? bhi(w) : blo(w);
        cnt += 1.0f;
    }
    atomicAdd(&g_hg[cur * HID + c], sum);
    if (c == 0) atomicAdd(&g_gcnt[cur], cnt);
}

__global__ void final_k(const float* __restrict__ p_pos,
                        const float* __restrict__ p_neg,
                        const float* __restrict__ W_fc,
                        float* __restrict__ out) {
    __shared__ float ss[N_GRAPHS][10];
    int t = threadIdx.x;
    if (t < N_GRAPHS * 10) {
        int g = t / 10;
        int p = t % 10;
        const float* P = (p < 5) ? (p_pos + p * HID) : (p_neg + (p - 5) * HID);
        float invc = 1.0f / fmaxf(g_gcnt[g], 1.0f);
        float d = 0.0f;
        for (int c = 0; c < HID; c++) {
            float diff = g_hg[g * HID + c] * invc - P[c];
            d += diff * diff;
        }
        ss[g][p] = logf((d + 1.0f) / (d + 1e-12f));
    }
    __syncthreads();
    if (t < N_GRAPHS) {
        float y = 0.0f;
        #pragma unroll
        for (int j = 0; j < 10; j++) y += ss[t][j] * W_fc[j];
        out[t] = 1.0f / (1.0f + expf(-y));
    }
}

// ---------------- launch: CSR build forked onto a side stream -------------
extern "C" void kernel_launch(void* const* d_in, const int* in_sizes, int n_in,
                              void* d_out, int out_size) {
    const float* h      = (const float*)d_in[0];
    const int*   src    = (const int*)d_in[1];
    const int*   dst    = (const int*)d_in[2];
    const int*   gid    = (const int*)d_in[3];
    const float* W_emb  = (const float*)d_in[4];
    const float* b_emb  = (const float*)d_in[5];
    const float* Ws     = (const float*)d_in[6];
    const float* bs     = (const float*)d_in[7];
    const float* p_pos  = (const float*)d_in[8];
    const float* p_neg  = (const float*)d_in[9];
    const float* W_fc   = (const float*)d_in[10];
    float* out = (float*)d_out;

    static cudaStream_t s1 = nullptr;
    static cudaEvent_t eFork = nullptr, eJoin = nullptr;
    if (s1 == nullptr) {
        cudaStreamCreateWithFlags(&s1, cudaStreamNonBlocking);
        cudaEventCreateWithFlags(&eFork, cudaEventDisableTiming);
        cudaEventCreateWithFlags(&eJoin, cudaEventDisableTiming);
    }

    bool fork = (s1 != nullptr && eFork != nullptr && eJoin != nullptr);
    cudaStream_t sb = fork ? s1 : (cudaStream_t)0;

    if (fork) {
        cudaEventRecord(eFork, 0);
        cudaStreamWaitEvent(sb, eFork, 0);
    }

    // branch B (side stream): CSR build + accumulator init
    init_k<<<(N_NODES + 255) / 256, 256, 0, sb>>>();
    deg_k<<<(N_EDGES + 255) / 256, 256, 0, sb>>>(dst);
    scanA_k<<<NB, 256, 0, sb>>>();
    scanB_k<<<1, 256, 0, sb>>>();
    scanC_k<<<NB, 256, 0, sb>>>();
    fill_k<<<(N_EDGES + 255) / 256, 256, 0, sb>>>(src, dst);

    // branch A (main stream): weight prep + embedding GEMM
    prep_k<<<(WF8_U32 + 255) / 256, 256>>>(W_emb, Ws);
    tgemm_k<0><<<MT64, 256>>>(h, b_emb, 0, 1);

    if (fork) {
        cudaEventRecord(eJoin, sb);
        cudaStreamWaitEvent(0, eJoin, 0);
    }

    for (int l = 0; l < N_LAYERS; l++) {
        agg_k<<<(N_NODES * 32 + 255) / 256, 256>>>();
        tgemm_k<1><<<MT64, 256>>>(nullptr, bs + (size_t)l * HID,
                                  EMB_F8 + l * LYR_F8,
                                  (l < N_LAYERS - 1) ? 1 : 0);
    }

    accum_k<<<NB, 256>>>(gid);
    final_k<<<1, 640>>>(p_pos, p_neg, W_fc, out);
}

// round 16
// speedup vs baseline: 1.0788x; 1.0006x over previous
#include <cuda_runtime.h>
#include <cuda_bf16.h>
#include <cstdint>

// ---------------- problem constants ----------------
#define N_NODES   50000
#define N_EDGES   800000
#define N_GRAPHS  64
#define IN_DIM    128
#define HID       256
#define N_LAYERS  4
#define NPAD      50048   // 64*782
#define MT64      782
#define NB        196

// fp8 fragment-ordered weights (u32 slots, each = 4 x e4m3)
#define EMB_F8    (4*32*32*2)     // ktiles(32-chunks)=4
#define LYR_F8    (16*32*32*2)    // ktiles=16
#define WF8_U32   (EMB_F8 + 4*LYR_F8)

#define XSCL 8.0f     // x stored in fp8 as 8*x
#define WSCL 16.0f    // W stored in fp8 as 16*W
#define INV_XW (1.0f/(XSCL*WSCL))
#define INV_W  (1.0f/WSCL)

#define ASTR 132      // smem A row stride in u32 (conflict-free fragment LDS)

// ---------------- device scratch ----------------
__device__ uint32_t g_xb[(size_t)NPAD * 128];   // bf16 canonical x
__device__ uint32_t g_xf8[(size_t)NPAD * 64];   // e4m3 8*x
__device__ uint32_t g_cf8[(size_t)NPAD * 64];   // e4m3 8*c
__device__ uint32_t g_wf8[WF8_U32];
__device__ int      g_deg[N_NODES];
__device__ int      g_rowoff[N_NODES + 1];
__device__ int      g_cursor[N_NODES];
__device__ int      g_csr[N_EDGES];
__device__ float    g_inv[N_NODES];
__device__ int      g_bsum[NB];
__device__ int      g_boff[NB];
__device__ float    g_hg[N_GRAPHS * HID];
__device__ float    g_gcnt[N_GRAPHS];

// ---------------- helpers ----------------
__device__ __forceinline__ uint32_t pk2(float lo, float hi) {
    uint32_t p;
    asm("cvt.rn.bf16x2.f32 %0, %1, %2;" : "=r"(p) : "f"(hi), "f"(lo));
    return p;
}
__device__ __forceinline__ float blo(uint32_t u) { return __uint_as_float(u << 16); }
__device__ __forceinline__ float bhi(uint32_t u) { return __uint_as_float(u & 0xffff0000u); }

__device__ __forceinline__ unsigned short pk_e2(float f0, float f1) {
    unsigned short d;
    asm("cvt.rn.satfinite.e4m3x2.f32 %0, %1, %2;" : "=h"(d) : "f"(f1), "f"(f0));
    return d;
}
__device__ __forceinline__ uint32_t pk_e4(float f0, float f1, float f2, float f3) {
    unsigned short lo = pk_e2(f0, f1), hi = pk_e2(f2, f3);
    uint32_t r;
    asm("mov.b32 %0, {%1, %2};" : "=r"(r) : "h"(lo), "h"(hi));
    return r;
}
__device__ __forceinline__ void acc_f8(uint32_t v, uint32_t& sA, uint32_t& sB) {
    unsigned short lo, hi;
    asm("mov.b32 {%0, %1}, %2;" : "=h"(lo), "=h"(hi) : "r"(v));
    uint32_t fA, fB;
    asm("cvt.rn.f16x2.e4m3x2 %0, %1;" : "=r"(fA) : "h"(lo));
    asm("cvt.rn.f16x2.e4m3x2 %0, %1;" : "=r"(fB) : "h"(hi));
    asm("add.rn.f16x2 %0, %0, %1;" : "+r"(sA) : "r"(fA));
    asm("add.rn.f16x2 %0, %0, %1;" : "+r"(sB) : "r"(fB));
}
__device__ __forceinline__ void hadd2(uint32_t& a, uint32_t b) {
    asm("add.rn.f16x2 %0, %0, %1;" : "+r"(a) : "r"(b));
}
__device__ __forceinline__ float2 up_h2(uint32_t v) {
    unsigned short lo, hi;
    asm("mov.b32 {%0, %1}, %2;" : "=h"(lo), "=h"(hi) : "r"(v));
    float a, b;
    asm("cvt.f32.f16 %0, %1;" : "=f"(a) : "h"(lo));
    asm("cvt.f32.f16 %0, %1;" : "=f"(b) : "h"(hi));
    return make_float2(a, b);
}

// fp8 MMA with f16 accumulators: d/c = {f16x2, f16x2} (2 regs)
__device__ __forceinline__ void mma_f8h(uint32_t* c, const uint32_t* a,
                                        uint32_t b0, uint32_t b1) {
    asm volatile(
        "mma.sync.aligned.m16n8k32.row.col.f16.e4m3.e4m3.f16 "
        "{%0,%1}, {%2,%3,%4,%5}, {%6,%7}, {%0,%1};"
        : "+r"(c[0]), "+r"(c[1])
        : "r"(a[0]), "r"(a[1]), "r"(a[2]), "r"(a[3]), "r"(b0), "r"(b1));
}

// non-coherent 64-bit load (B weights are read-only during tgemm)
__device__ __forceinline__ uint2 ldg_nc2(const uint2* p) {
    uint2 v;
    asm("ld.global.nc.v2.u32 {%0, %1}, [%2];"
        : "=r"(v.x), "=r"(v.y) : "l"(p));
    return v;
}

// ---------------- init ----------------
__global__ void init_k() {
    int i = blockIdx.x * blockDim.x + threadIdx.x;
    if (i < N_NODES) g_deg[i] = 0;
    if (i < N_GRAPHS * HID) g_hg[i] = 0.0f;
    if (i < N_GRAPHS) g_gcnt[i] = 0.0f;
}

// ---------------- weight prep: x16 scale, e4m3, fragment-ordered ----------
__global__ void prep_k(const float* __restrict__ W_emb,
                       const float* __restrict__ Ws) {
    int i = blockIdx.x * blockDim.x + threadIdx.x;
    if (i >= WF8_U32) return;
    const float* Wsrc;
    int r;
    if (i < EMB_F8) { r = i; Wsrc = W_emb; }
    else {
        int j = i - EMB_F8;
        int l = j / LYR_F8;
        r = j % LYR_F8;
        Wsrc = Ws + (size_t)l * 512 * 256;
    }
    int reg = r & 1;
    int lane = (r >> 1) & 31;
    int tile = r >> 6;
    int nt = tile & 31;
    int kt = tile >> 5;
    int k0 = kt * 32 + (lane & 3) * 4 + reg * 16;
    int n = nt * 8 + (lane >> 2);
    float w0 = Wsrc[(size_t)k0 * 256 + n] * WSCL;
    float w1 = Wsrc[(size_t)(k0 + 1) * 256 + n] * WSCL;
    float w2 = Wsrc[(size_t)(k0 + 2) * 256 + n] * WSCL;
    float w3 = Wsrc[(size_t)(k0 + 3) * 256 + n] * WSCL;
    g_wf8[i] = pk_e4(w0, w1, w2, w3);
}

// ---------------- CSR build ----------------
__global__ void deg_k(const int* __restrict__ dst) {
    int i = blockIdx.x * blockDim.x + threadIdx.x;
    if (i < N_EDGES) atomicAdd(&g_deg[dst[i]], 1);
}

__device__ __forceinline__ int block_scan_incl(int v, int* wt) {
    int t = threadIdx.x;
    int s = v;
    #pragma unroll
    for (int off = 1; off < 32; off <<= 1) {
        int u = __shfl_up_sync(0xffffffffu, s, off);
        if ((t & 31) >= off) s += u;
    }
    if ((t & 31) == 31) wt[t >> 5] = s;
    __syncthreads();
    if (t < 8) {
        int w = wt[t];
        #pragma unroll
        for (int off = 1; off < 8; off <<= 1) {
            int u = __shfl_up_sync(0xffu, w, off);
            if (t >= off) w += u;
        }
        wt[t] = w;
    }
    __syncthreads();
    return s + ((t >= 32) ? wt[(t >> 5) - 1] : 0);
}

__global__ void scanA_k() {
    __shared__ int wt[8];
    int i = blockIdx.x * 256 + threadIdx.x;
    int v = (i < N_NODES) ? g_deg[i] : 0;
    int incl = block_scan_incl(v, wt);
    if (i < N_NODES) g_rowoff[i] = incl - v;
    if (threadIdx.x == 255) g_bsum[blockIdx.x] = incl;
}

__global__ void scanB_k() {
    __shared__ int wt[8];
    int t = threadIdx.x;
    int v = (t < NB) ? g_bsum[t] : 0;
    int incl = block_scan_incl(v, wt);
    if (t < NB) g_boff[t] = incl - v;
    if (t == NB - 1) g_rowoff[N_NODES] = incl;
}

__global__ void scanC_k() {
    int i = blockIdx.x * 256 + threadIdx.x;
    if (i >= N_NODES) return;
    int ro = g_rowoff[i] + g_boff[blockIdx.x];
    g_rowoff[i] = ro;
    g_cursor[i] = ro;
    int d = g_deg[i];
    g_inv[i] = 1.0f / (float)(d > 0 ? d : 1);
}

__global__ void fill_k(const int* __restrict__ src, const int* __restrict__ dst) {
    int i = blockIdx.x * blockDim.x + threadIdx.x;
    if (i < N_EDGES) {
        int d = dst[i];
        int p = atomicAdd(&g_cursor[d], 1);
        g_csr[p] = src[i];
    }
}

// ---------------- mean aggregation: half-warp rows (R7/R11/R13 proven) -----
__global__ void __launch_bounds__(256) agg_k() {
    int gw = (blockIdx.x * blockDim.x + threadIdx.x) >> 5;
    int lane = threadIdx.x & 31;
    if (gw >= N_NODES) return;
    int half = lane >> 4;
    int hl = lane & 15;
    int beg = g_rowoff[gw];
    int end = g_rowoff[gw + 1];
    uint32_t s[8] = {0, 0, 0, 0, 0, 0, 0, 0};
    const uint4* xf = (const uint4*)g_xf8;
    #pragma unroll 2
    for (int j = beg + half; j < end; j += 2) {
        int sn = g_csr[j];
        uint4 v = xf[(size_t)sn * 16 + hl];
        acc_f8(v.x, s[0], s[1]);
        acc_f8(v.y, s[2], s[3]);
        acc_f8(v.z, s[4], s[5]);
        acc_f8(v.w, s[6], s[7]);
    }
    #pragma unroll
    for (int q = 0; q < 8; q++) {
        uint32_t o = __shfl_xor_sync(0xffffffffu, s[q], 16);
        hadd2(s[q], o);
    }
    if (half == 0) {
        float inv = g_inv[gw];
        float2 a0 = up_h2(s[0]), a1 = up_h2(s[1]);
        float2 a2 = up_h2(s[2]), a3 = up_h2(s[3]);
        float2 a4 = up_h2(s[4]), a5 = up_h2(s[5]);
        float2 a6 = up_h2(s[6]), a7 = up_h2(s[7]);
        uint4 o;
        o.x = pk_e4(a0.x * inv, a0.y * inv, a1.x * inv, a1.y * inv);
        o.y = pk_e4(a2.x * inv, a2.y * inv, a3.x * inv, a3.y * inv);
        o.z = pk_e4(a4.x * inv, a4.y * inv, a5.x * inv, a5.y * inv);
        o.w = pk_e4(a6.x * inv, a6.y * inv, a7.x * inv, a7.y * inv);
        ((uint4*)g_cf8)[(size_t)gw * 16 + hl] = o;
    }
}

// ---------------- fp8 mma.sync fused GEMM, smem A + f16 acc ----------------
// CTA: 256 thr = 8 warps (2M x 4N); tile 64 rows x 256 cols; K-chunk = 32.
// B loads use ld.global.nc (read-only) to enable L1 caching across CTAs.
// wf8: skip fp8 shadow stores (dead after the last layer).
template <int MODE>
__global__ void __launch_bounds__(256, 3) tgemm_k(const float* __restrict__ Aext,
                                                  const float* __restrict__ bias,
                                                  int fragoff, int wf8) {
    const int NCH = MODE ? 16 : 4;

    __shared__ uint32_t As[64 * ASTR];
    __shared__ float ssq[64];
    __shared__ float rinv[64];
    __shared__ float biasS[256];

    int tid = threadIdx.x;
    int lane = tid & 31;
    int wid = tid >> 5;
    int wm = wid >> 2;
    int wn = wid & 3;
    int g = lane >> 2;
    int t = lane & 3;
    int row0 = blockIdx.x * 64;

    if (tid < 64) ssq[tid] = 0.0f;
    if (tid < 128) {
        float2 bv = ((const float2*)bias)[tid];
        biasS[2 * tid] = bv.x;
        biasS[2 * tid + 1] = bv.y;
    }

    // ---- stage A into smem (coalesced) ----
    if (MODE == 0) {
        #pragma unroll
        for (int it = 0; it < 8; it++) {
            int idx = it * 256 + tid;
            int r = idx >> 5;
            int cu = idx & 31;
            int gr = row0 + r;
            float4 f = (gr < N_NODES)
                ? ((const float4*)(Aext + (size_t)gr * 128))[cu]
                : make_float4(0.f, 0.f, 0.f, 0.f);
            As[r * ASTR + cu] = pk_e4(f.x, f.y, f.z, f.w);
        }
    } else {
        #pragma unroll
        for (int it = 0; it < 4; it++) {
            int idx = it * 256 + tid;
            int r = idx >> 4;
            int q = idx & 15;
            uint4 vx = ((const uint4*)g_xf8)[(size_t)(row0 + r) * 16 + q];
            *(uint4*)&As[r * ASTR + q * 4] = vx;
            uint4 vc = ((const uint4*)g_cf8)[(size_t)(row0 + r) * 16 + q];
            *(uint4*)&As[r * ASTR + 64 + q * 4] = vc;
        }
    }
    __syncthreads();

    uint32_t acc[2][8][2];   // f16x2 pairs
    #pragma unroll
    for (int m = 0; m < 2; m++)
        #pragma unroll
        for (int j = 0; j < 8; j++) {
            acc[m][j][0] = 0u;
            acc[m][j][1] = 0u;
        }

    const uint2* WF = (const uint2*)(g_wf8 + fragoff);
    int bbase = (wn * 8) * 32 + lane;

    #pragma unroll
    for (int ch = 0; ch < NCH; ch++) {
        int base = ch * 8;
        uint32_t ah[2][4];
        #pragma unroll
        for (int mt = 0; mt < 2; mt++) {
            int rl = wm * 32 + mt * 16 + g;
            const uint32_t* p = &As[rl * ASTR + base + t];
            ah[mt][0] = p[0];
            ah[mt][1] = p[8 * ASTR];
            ah[mt][2] = p[4];
            ah[mt][3] = p[8 * ASTR + 4];
        }

        uint2 bh[8];
        const uint2* ph = WF + (size_t)(ch * 32) * 32 + bbase;
        #pragma unroll
        for (int j = 0; j < 8; j++) bh[j] = ldg_nc2(ph + j * 32);

        #pragma unroll
        for (int mt = 0; mt < 2; mt++)
            #pragma unroll
            for (int j = 0; j < 8; j++)
                mma_f8h(acc[mt][j], ah[mt], bh[j].x, bh[j].y);
    }

    __syncthreads();

    const float cs = MODE ? INV_XW : INV_W;

    if (MODE == 1) {
        #pragma unroll
        for (int mt = 0; mt < 2; mt++) {
            float p0 = 0.f, p1 = 0.f;
            #pragma unroll
            for (int j = 0; j < 8; j++) {
                int n0 = wn * 64 + j * 8 + 2 * t;
                float b0 = biasS[n0], b1 = biasS[n0 + 1];
                float2 lo = up_h2(acc[mt][j][0]);
                float2 hi = up_h2(acc[mt][j][1]);
                float v0 = lo.x * cs + b0;
                float v1 = lo.y * cs + b1;
                float v2 = hi.x * cs + b0;
                float v3 = hi.y * cs + b1;
                p0 += v0 * v0 + v1 * v1;
                p1 += v2 * v2 + v3 * v3;
            }
            p0 += __shfl_xor_sync(0xffffffffu, p0, 1);
            p0 += __shfl_xor_sync(0xffffffffu, p0, 2);
            p1 += __shfl_xor_sync(0xffffffffu, p1, 1);
            p1 += __shfl_xor_sync(0xffffffffu, p1, 2);
            if (t == 0) {
                atomicAdd(&ssq[wm * 32 + mt * 16 + g], p0);
                atomicAdd(&ssq[wm * 32 + mt * 16 + 8 + g], p1);
            }
        }
        __syncthreads();
        if (tid < 64) rinv[tid] = 1.0f / fmaxf(sqrtf(ssq[tid]), 1e-12f);
        __syncthreads();
    }

    unsigned short* xf16 = (unsigned short*)g_xf8;

    #pragma unroll
    for (int mt = 0; mt < 2; mt++) {
        int rl = wm * 32 + mt * 16 + g;
        int r = row0 + rl;
        float i0 = (MODE == 1) ? rinv[rl] : 0.f;
        float i1 = (MODE == 1) ? rinv[rl + 8] : 0.f;
        #pragma unroll
        for (int j = 0; j < 8; j++) {
            int n0 = wn * 64 + j * 8 + 2 * t;
            float b0 = biasS[n0], b1 = biasS[n0 + 1];
            float2 lo = up_h2(acc[mt][j][0]);
            float2 hi = up_h2(acc[mt][j][1]);
            float v0 = lo.x * cs + b0;
            float v1 = lo.y * cs + b1;
            float v2 = hi.x * cs + b0;
            float v3 = hi.y * cs + b1;
            size_t u0 = (size_t)r * 128 + n0 / 2;
            size_t u1 = (size_t)(r + 8) * 128 + n0 / 2;
            if (MODE == 0) {
                g_xb[u0] = pk2(v0, v1);
                g_xb[u1] = pk2(v2, v3);
                xf16[u0] = pk_e2(v0 * XSCL, v1 * XSCL);
                xf16[u1] = pk_e2(v2 * XSCL, v3 * XSCL);
            } else {
                uint32_t xw0 = g_xb[u0];
                float o0 = blo(xw0) + fmaxf(v0, 0.f) * i0;
                float o1 = bhi(xw0) + fmaxf(v1, 0.f) * i0;
                g_xb[u0] = pk2(o0, o1);
                uint32_t xw1 = g_xb[u1];
                float o2 = blo(xw1) + fmaxf(v2, 0.f) * i1;
                float o3 = bhi(xw1) + fmaxf(v3, 0.f) * i1;
                g_xb[u1] = pk2(o2, o3);
                if (wf8) {
                    xf16[u0] = pk_e2(o0 * XSCL, o1 * XSCL);
                    xf16[u1] = pk_e2(o2 * XSCL, o3 * XSCL);
                }
            }
        }
    }
}

// ---------------- graph mean pool (vectorized: 1 u32 = 2 cols per thread) --
__global__ void accum_k(const int* __restrict__ gid) {
    int b = blockIdx.x;
    int c2 = threadIdx.x;        // 0..127, u32 column index
    int n0 = b * 256;
    int n1 = min(n0 + 256, N_NODES);
    float s0 = 0.0f, s1 = 0.0f, cnt = 0.0f;
    int cur = gid[n0];
    for (int n = n0; n < n1; n++) {
        int gg = gid[n];
        if (gg != cur) {
            atomicAdd(&g_hg[cur * HID + 2 * c2], s0);
            atomicAdd(&g_hg[cur * HID + 2 * c2 + 1], s1);
            if (c2 == 0) atomicAdd(&g_gcnt[cur], cnt);
            s0 = 0.0f; s1 = 0.0f; cnt = 0.0f; cur = gg;
        }
        uint32_t w = g_xb[(size_t)n * 128 + c2];
        s0 += blo(w);
        s1 += bhi(w);
        cnt += 1.0f;
    }
    atomicAdd(&g_hg[cur * HID + 2 * c2], s0);
    atomicAdd(&g_hg[cur * HID + 2 * c2 + 1], s1);
    if (c2 == 0) atomicAdd(&g_gcnt[cur], cnt);
}

__global__ void final_k(const float* __restrict__ p_pos,
                        const float* __restrict__ p_neg,
                        const float* __restrict__ W_fc,
                        float* __restrict__ out) {
    __shared__ float ss[N_GRAPHS][10];
    int t = threadIdx.x;
    if (t < N_GRAPHS * 10) {
        int g = t / 10;
        int p = t % 10;
        const float* P = (p < 5) ? (p_pos + p * HID) : (p_neg + (p - 5) * HID);
        float invc = 1.0f / fmaxf(g_gcnt[g], 1.0f);
        float d = 0.0f;
        for (int c = 0; c < HID; c++) {
            float diff = g_hg[g * HID + c] * invc - P[c];
            d += diff * diff;
        }
        ss[g][p] = logf((d + 1.0f) / (d + 1e-12f));
    }
    __syncthreads();
    if (t < N_GRAPHS) {
        float y = 0.0f;
        #pragma unroll
        for (int j = 0; j < 10; j++) y += ss[t][j] * W_fc[j];
        out[t] = 1.0f / (1.0f + expf(-y));
    }
}

// ---------------- launch: CSR build forked onto a side stream -------------
extern "C" void kernel_launch(void* const* d_in, const int* in_sizes, int n_in,
                              void* d_out, int out_size) {
    const float* h      = (const float*)d_in[0];
    const int*   src    = (const int*)d_in[1];
    const int*   dst    = (const int*)d_in[2];
    const int*   gid    = (const int*)d_in[3];
    const float* W_emb  = (const float*)d_in[4];
    const float* b_emb  = (const float*)d_in[5];
    const float* Ws     = (const float*)d_in[6];
    const float* bs     = (const float*)d_in[7];
    const float* p_pos  = (const float*)d_in[8];
    const float* p_neg  = (const float*)d_in[9];
    const float* W_fc   = (const float*)d_in[10];
    float* out = (float*)d_out;

    static cudaStream_t s1 = nullptr;
    static cudaEvent_t eFork = nullptr, eJoin = nullptr;
    if (s1 == nullptr) {
        cudaStreamCreateWithFlags(&s1, cudaStreamNonBlocking);
        cudaEventCreateWithFlags(&eFork, cudaEventDisableTiming);
        cudaEventCreateWithFlags(&eJoin, cudaEventDisableTiming);
    }

    bool fork = (s1 != nullptr && eFork != nullptr && eJoin != nullptr);
    cudaStream_t sb = fork ? s1 : (cudaStream_t)0;

    if (fork) {
        cudaEventRecord(eFork, 0);
        cudaStreamWaitEvent(sb, eFork, 0);
    }

    // branch B (side stream): CSR build + accumulator init
    init_k<<<(N_NODES + 255) / 256, 256, 0, sb>>>();
    deg_k<<<(N_EDGES + 255) / 256, 256, 0, sb>>>(dst);
    scanA_k<<<NB, 256, 0, sb>>>();
    scanB_k<<<1, 256, 0, sb>>>();
    scanC_k<<<NB, 256, 0, sb>>>();
    fill_k<<<(N_EDGES + 255) / 256, 256, 0, sb>>>(src, dst);

    // branch A (main stream): weight prep + embedding GEMM
    prep_k<<<(WF8_U32 + 255) / 256, 256>>>(W_emb, Ws);
    tgemm_k<0><<<MT64, 256>>>(h, b_emb, 0, 1);

    if (fork) {
        cudaEventRecord(eJoin, sb);
        cudaStreamWaitEvent(0, eJoin, 0);
    }

    for (int l = 0; l < N_LAYERS; l++) {
        agg_k<<<(N_NODES * 32 + 255) / 256, 256>>>();
        tgemm_k<1><<<MT64, 256>>>(nullptr, bs + (size_t)l * HID,
                                  EMB_F8 + l * LYR_F8,
                                  (l < N_LAYERS - 1) ? 1 : 0);
    }

    accum_k<<<NB, 128>>>(gid);
    final_k<<<1, 640>>>(p_pos, p_neg, W_fc, out);
}